// round 12
// baseline (speedup 1.0000x reference)
#include <cuda_runtime.h>
#include <cuda_fp16.h>
#include <cstdint>
#include <cstddef>

// ---------------- problem constants ----------------
#define Jn 24
#define Cc 32
#define KT 15
#define Bn 32
#define Tn 4096
#define NP 12          // pooled pairs
#define TT 256         // output t per CTA
#define UROWS 272      // staged t rows: u stores x[t0-8+u]
#define NEG 0.2f

// A (weight) images: per (pair, tap, jj): 32 rows x 104 halves (96 + 8 pad)
#define APITCHH 104
#define APITCHB 208
#define AIMG1   (32 * APITCHB)       // 6656 B per out-joint
#define WIMG    (2 * AIMG1)          // 13312 B per (pair, tap)

// smem layout (bytes)
#define SM_X     0
#define X_BYTES  (UROWS * 256)       // 69632  ([u][128 ci] fp16, interleaved+swizzled)
#define SM_W     X_BYTES
#define SM_TOTAL (SM_W + 3 * WIMG)   // 109568
#define YPITCH   264                 // floats; ybuf reuses X region

// Repacked weights: per (pair, tap) one WIMG image (jj-major), zero-padded.
__device__ __align__(16) __half g_wpk[NP * KT * 2 * 32 * APITCHH];   // 2.4 MB

// ---------------- helpers ----------------
__device__ __forceinline__ uint32_t smem_u32(const void* p) {
    uint32_t a;
    asm("{ .reg .u64 t; cvta.to.shared.u64 t, %1; cvt.u32.u64 %0, t; }" : "=r"(a) : "l"(p));
    return a;
}
__device__ __forceinline__ void ldm4(uint32_t a[4], uint32_t addr) {
    asm volatile("ldmatrix.sync.aligned.m8n8.x4.shared.b16 {%0,%1,%2,%3}, [%4];"
                 : "=r"(a[0]), "=r"(a[1]), "=r"(a[2]), "=r"(a[3]) : "r"(addr));
}
__device__ __forceinline__ void mma16816(float d[4], const uint32_t a[4],
                                         uint32_t b0, uint32_t b1) {
    asm volatile("mma.sync.aligned.m16n8k16.row.col.f32.f16.f16.f32 "
                 "{%0,%1,%2,%3}, {%4,%5,%6,%7}, {%8,%9}, {%0,%1,%2,%3};"
                 : "+f"(d[0]), "+f"(d[1]), "+f"(d[2]), "+f"(d[3])
                 : "r"(a[0]), "r"(a[1]), "r"(a[2]), "r"(a[3]), "r"(b0), "r"(b1));
}
__device__ __forceinline__ void cp_tile(uint32_t dst, const char* src, int tid) {
    for (int i = tid; i < WIMG / 16; i += 256)
        asm volatile("cp.async.cg.shared.global [%0], [%1], 16;"
                     :: "r"(dst + (uint32_t)(i * 16)), "l"(src + (size_t)i * 16) : "memory");
    asm volatile("cp.async.commit_group;" ::: "memory");
}

// ---------------- weight repack ----------------
// Image element (jj, r, ci): w[(2g+jj)*32+r][( (2g+jj-1) + ci/32 )*32 + ci%32][k]
__global__ void repack_w(const float* __restrict__ w) {
    int g = blockIdx.x / KT, k = blockIdx.x % KT;
    __half* img = g_wpk + (size_t)blockIdx.x * (2 * 32 * APITCHH);
    for (int e = threadIdx.x; e < 2 * 32 * APITCHH; e += 256) {
        int jj = e / (32 * APITCHH);
        int rem = e - jj * (32 * APITCHH);
        int r = rem / APITCHH, ci = rem - r * APITCHH;
        float v = 0.f;
        if (ci < 96) {
            int oj = 2 * g + jj, ij = oj - 1 + (ci >> 5);
            if (ij >= 0 && ij < Jn)
                v = w[((size_t)(oj * Cc + r) * (Jn * Cc) + ij * Cc + (ci & 31)) * KT + k];
        }
        img[e] = __float2half_rn(v);
    }
}

// ---------------- main HMMA kernel ----------------
__global__ void __launch_bounds__(256, 2)
skel_hmma_kernel(const float* __restrict__ x, const float* __restrict__ bias,
                 float* __restrict__ out) {
    extern __shared__ char smem[];
    const uint32_t sb = smem_u32(smem);
    const int tid = threadIdx.x, wid = tid >> 5, lane = tid & 31;
    const int r4 = lane & 3, q = lane >> 2;
    const int t0 = blockIdx.x * TT;
    const int g = blockIdx.y, b = blockIdx.z;
    const int nbase = wid * 32;

    // ---- prefetch W stages 0,1 ----
    const char* wg = (const char*)g_wpk + (size_t)g * KT * WIMG;
    cp_tile(sb + SM_W, wg, tid);
    cp_tile(sb + SM_W + WIMG, wg + WIMG, tid);

    // ---- stage X: fp32 -> fp16 into interleaved+swizzled [u][ci] image ----
    // logical ci -> word w = ci>>1; octet o = w>>3, s = w&7
    // storage word w' = 8o + 2(s&3) + (s>>2); dword dd = w'>>1 = 4o + (s&3)
    // swizzled dword dd' = dd ^ ((u&7)<<2); byte = u*256 + dd'*8 + (w'&1)*4 + (ci&1)*2
    {
        const int jb = 2 * g - 1;
        for (int i = tid; i < 128 * (UROWS / 4); i += 256) {
            int ci = i / (UROWS / 4), tq = i - ci * (UROWS / 4);
            int ij = jb + (ci >> 5);
            int tt = t0 - 8 + 4 * tq;
            float4 v = make_float4(0.f, 0.f, 0.f, 0.f);
            if (ij >= 0 && ij < Jn && tt >= 0 && tt < Tn)
                v = *(const float4*)(x + ((size_t)b * (Jn * Cc) + ij * Cc + (ci & 31)) * Tn + tt);
            int w_ = ci >> 1, o = w_ >> 3, s = w_ & 7;
            int wp = 8 * o + 2 * (s & 3) + (s >> 2);
            uint32_t dd = (uint32_t)(wp >> 1);
            uint32_t sub = (uint32_t)((wp & 1) * 4 + (ci & 1) * 2);
            float vv[4] = {v.x, v.y, v.z, v.w};
#pragma unroll
            for (int e = 0; e < 4; e++) {
                int u = 4 * tq + e;
                uint32_t addr = sb + SM_X + (uint32_t)(u << 8) +
                                ((dd ^ (uint32_t)((u & 7) << 2)) << 3) + sub;
                __half h = __float2half_rn(vv[e]);
                unsigned short hs = *(unsigned short*)&h;
                asm volatile("st.shared.b16 [%0], %1;" :: "r"(addr), "h"(hs));
            }
        }
    }

    // ---- mainloop ----
    float acc[2][2][4][4];
#pragma unroll
    for (int jj = 0; jj < 2; jj++)
#pragma unroll
        for (int mt = 0; mt < 2; mt++)
#pragma unroll
            for (int j = 0; j < 4; j++)
#pragma unroll
                for (int e = 0; e < 4; e++) acc[jj][mt][j][e] = 0.f;

    uint32_t arel[2];
#pragma unroll
    for (int mt = 0; mt < 2; mt++)
        arel[mt] = (uint32_t)((mt * 16 + (lane & 15)) * APITCHB + (lane >> 4) * 16);

    for (int k = 0; k < KT; k++) {
        if (k < KT - 1) asm volatile("cp.async.wait_group 1;" ::: "memory");
        else            asm volatile("cp.async.wait_group 0;" ::: "memory");
        __syncthreads();                               // stage k + X visible; tap k-1 reads done
        if (k + 2 < KT)
            cp_tile(sb + SM_W + (uint32_t)(((k + 2) % 3) * WIMG),
                    wg + (size_t)(k + 2) * WIMG, tid);

        uint32_t aimg = sb + SM_W + (uint32_t)((k % 3) * WIMG);
        uint32_t u7 = (uint32_t)((q + k + 1) & 7);
        uint32_t pb[4];
#pragma unroll
        for (int j = 0; j < 4; j++) {
            int u = nbase + j * 8 + q + k + 1;
            pb[j] = sb + SM_X + (uint32_t)(u << 8) + (uint32_t)(r4 * 8);
        }
#pragma unroll
        for (int o = 0; o < 8; o++) {
            uint32_t off = (((uint32_t)o ^ u7) << 5);
            uint32_t bx[4][2];
#pragma unroll
            for (int j = 0; j < 4; j++)
                asm volatile("ld.shared.v2.b32 {%0,%1}, [%2];"
                             : "=r"(bx[j][0]), "=r"(bx[j][1]) : "r"(pb[j] + off));
            uint32_t A0[4], A1[4], A2[4], A3[4];
            if (o < 6) {
                ldm4(A0, aimg + arel[0] + (uint32_t)(o * 32));
                ldm4(A1, aimg + arel[1] + (uint32_t)(o * 32));
            }
            if (o >= 2) {
                ldm4(A2, aimg + AIMG1 + arel[0] + (uint32_t)((o - 2) * 32));
                ldm4(A3, aimg + AIMG1 + arel[1] + (uint32_t)((o - 2) * 32));
            }
#pragma unroll
            for (int j = 0; j < 4; j++) {
                if (o < 6) {
                    mma16816(acc[0][0][j], A0, bx[j][0], bx[j][1]);
                    mma16816(acc[0][1][j], A1, bx[j][0], bx[j][1]);
                }
                if (o >= 2) {
                    mma16816(acc[1][0][j], A2, bx[j][0], bx[j][1]);
                    mma16816(acc[1][1][j], A3, bx[j][0], bx[j][1]);
                }
            }
        }
    }

    __syncthreads();   // all B/A reads done before smem reuse as ybuf

    // ---- epilogue: pool jj0+jj1 + bias + LeakyReLU -> ybuf -> coalesced STG
    float bp[2][2];
#pragma unroll
    for (int mt = 0; mt < 2; mt++)
#pragma unroll
        for (int h = 0; h < 2; h++) {
            int ch = mt * 16 + h * 8 + q;
            bp[mt][h] = 0.5f * (bias[g * 64 + ch] + bias[g * 64 + 32 + ch]);
        }
    float* ybuf = (float*)smem;
#pragma unroll
    for (int mt = 0; mt < 2; mt++)
#pragma unroll
        for (int j = 0; j < 4; j++) {
            int col = nbase + j * 8 + 2 * r4;
#pragma unroll
            for (int h = 0; h < 2; h++) {
                float p0 = 0.5f * (acc[0][mt][j][2 * h]     + acc[1][mt][j][2 * h])     + bp[mt][h];
                float p1 = 0.5f * (acc[0][mt][j][2 * h + 1] + acc[1][mt][j][2 * h + 1]) + bp[mt][h];
                p0 = (p0 >= 0.f) ? p0 : NEG * p0;
                p1 = (p1 >= 0.f) ? p1 : NEG * p1;
                int ch = mt * 16 + h * 8 + q;
                *(float2*)&ybuf[ch * YPITCH + col] = make_float2(p0, p1);
            }
        }
    __syncthreads();
#pragma unroll
    for (int it = 0; it < 8; it++) {
        int f = it * 256 + tid;
        int row = f >> 6, c4 = (f & 63) << 2;
        float4 v = *(float4*)&ybuf[row * YPITCH + c4];
        *(float4*)(out + ((size_t)b * (NP * Cc) + g * Cc + row) * Tn + t0 + c4) = v;
    }
}

// ---------------- launch ----------------
extern "C" void kernel_launch(void* const* d_in, const int* in_sizes, int n_in,
                              void* d_out, int out_size) {
    const float* x    = (const float*)d_in[0];
    const float* w    = (const float*)d_in[1];
    const float* bias = (const float*)d_in[2];
    // d_in[3] = mask (static block-tridiagonal), d_in[4] = pool_pairs (consecutive)
    float* out = (float*)d_out;

    cudaFuncSetAttribute(skel_hmma_kernel,
                         cudaFuncAttributeMaxDynamicSharedMemorySize, SM_TOTAL);

    repack_w<<<NP * KT, 256>>>(w);
    dim3 grid(Tn / TT, NP, Bn);
    skel_hmma_kernel<<<grid, 256, SM_TOTAL>>>(x, bias, out);
}

// round 17
// speedup vs baseline: 1.6252x; 1.6252x over previous
#include <cuda_runtime.h>
#include <cuda_fp16.h>
#include <cstdint>
#include <cstddef>

// ---------------- problem constants ----------------
#define Jn 24
#define Cc 32
#define KT 15
#define Bn 32
#define Tn 4096
#define NP 12          // pooled pairs
#define TT 256         // output t per CTA
#define UROWS 272      // staged t rows: u stores x[t0-8+u]
#define NEG 0.2f

// A (weight) images: per (pair, tap, jj): 32 rows x 104 halves (96 + 8 pad)
#define APITCHH 104
#define APITCHB 208
#define AIMG1   (32 * APITCHB)       // 6656 B per out-joint
#define WIMG    (2 * AIMG1)          // 13312 B per (pair, tap)

// smem layout (bytes)
#define SM_X     0
#define X_BYTES  (UROWS * 256)       // 69632  ([u][128 ci] fp16, R10 swizzle)
#define SM_W     X_BYTES
#define SM_TOTAL (SM_W + 3 * WIMG)   // 109568
#define YPITCH   264                 // floats; ybuf reuses X region

// Repacked weights: per (pair, tap) one WIMG image (jj-major), zero-padded.
__device__ __align__(16) __half g_wpk[NP * KT * 2 * 32 * APITCHH];   // 2.4 MB

// ---------------- helpers ----------------
__device__ __forceinline__ uint32_t smem_u32(const void* p) {
    uint32_t a;
    asm("{ .reg .u64 t; cvta.to.shared.u64 t, %1; cvt.u32.u64 %0, t; }" : "=r"(a) : "l"(p));
    return a;
}
__device__ __forceinline__ void ldm4(uint32_t a[4], uint32_t addr) {
    asm volatile("ldmatrix.sync.aligned.m8n8.x4.shared.b16 {%0,%1,%2,%3}, [%4];"
                 : "=r"(a[0]), "=r"(a[1]), "=r"(a[2]), "=r"(a[3]) : "r"(addr));
}
__device__ __forceinline__ void mma16816(float d[4], const uint32_t a[4],
                                         uint32_t b0, uint32_t b1) {
    asm volatile("mma.sync.aligned.m16n8k16.row.col.f32.f16.f16.f32 "
                 "{%0,%1,%2,%3}, {%4,%5,%6,%7}, {%8,%9}, {%0,%1,%2,%3};"
                 : "+f"(d[0]), "+f"(d[1]), "+f"(d[2]), "+f"(d[3])
                 : "r"(a[0]), "r"(a[1]), "r"(a[2]), "r"(a[3]), "r"(b0), "r"(b1));
}
__device__ __forceinline__ void cp_tile(uint32_t dst, const char* src, int tid) {
    for (int i = tid; i < WIMG / 16; i += 256)
        asm volatile("cp.async.cg.shared.global [%0], [%1], 16;"
                     :: "r"(dst + (uint32_t)(i * 16)), "l"(src + (size_t)i * 16) : "memory");
    asm volatile("cp.async.commit_group;" ::: "memory");
}
// R10 word-granular swizzle: word' = word ^ ((u&7)<<2) ^ ((u>>3)&3)  (proven conflict-free)
__device__ __forceinline__ uint32_t xsw(int u) {
    return (uint32_t)((((u) & 7) << 2) ^ (((u) >> 3) & 3));
}

// ---------------- weight repack ----------------
// Image element (jj, r, ci): w[(2g+jj)*32+r][( (2g+jj-1) + ci/32 )*32 + ci%32][k]
__global__ void repack_w(const float* __restrict__ w) {
    int g = blockIdx.x / KT, k = blockIdx.x % KT;
    __half* img = g_wpk + (size_t)blockIdx.x * (2 * 32 * APITCHH);
    for (int e = threadIdx.x; e < 2 * 32 * APITCHH; e += 256) {
        int jj = e / (32 * APITCHH);
        int rem = e - jj * (32 * APITCHH);
        int r = rem / APITCHH, ci = rem - r * APITCHH;
        float v = 0.f;
        if (ci < 96) {
            int oj = 2 * g + jj, ij = oj - 1 + (ci >> 5);
            if (ij >= 0 && ij < Jn)
                v = w[((size_t)(oj * Cc + r) * (Jn * Cc) + ij * Cc + (ci & 31)) * KT + k];
        }
        img[e] = __float2half_rn(v);
    }
}

// ---------------- main HMMA kernel ----------------
__global__ void __launch_bounds__(256, 2)
skel_hmma_kernel(const float* __restrict__ x, const float* __restrict__ bias,
                 float* __restrict__ out) {
    extern __shared__ char smem[];
    const uint32_t sb = smem_u32(smem);
    const int tid = threadIdx.x, wid = tid >> 5, lane = tid & 31;
    const int r4 = lane & 3, q = lane >> 2;
    const int t0 = blockIdx.x * TT;
    const int g = blockIdx.y, b = blockIdx.z;
    const int nbase = wid * 32;

    // ---- prefetch W stages 0,1 ----
    const char* wg = (const char*)g_wpk + (size_t)g * KT * WIMG;
    cp_tile(sb + SM_W, wg, tid);
    cp_tile(sb + SM_W + WIMG, wg + WIMG, tid);

    // ---- stage X: fp32 -> fp16 into swizzled [u][ci] image (R10 layout) ----
    {
        const int jb = 2 * g - 1;
        for (int i = tid; i < 128 * (UROWS / 4); i += 256) {
            int ci = i / (UROWS / 4), tq = i - ci * (UROWS / 4);
            int ij = jb + (ci >> 5);
            int tt = t0 - 8 + 4 * tq;
            float4 v = make_float4(0.f, 0.f, 0.f, 0.f);
            if (ij >= 0 && ij < Jn && tt >= 0 && tt < Tn)
                v = *(const float4*)(x + ((size_t)b * (Jn * Cc) + ij * Cc + (ci & 31)) * Tn + tt);
            float vv[4] = {v.x, v.y, v.z, v.w};
            int wword = ci >> 1, hb2 = (ci & 1) * 2;
#pragma unroll
            for (int e = 0; e < 4; e++) {
                int u = 4 * tq + e;
                uint32_t addr = sb + SM_X + (uint32_t)(u << 8) +
                                ((((uint32_t)wword ^ xsw(u)) << 2) | (uint32_t)hb2);
                __half h = __float2half_rn(vv[e]);
                unsigned short hs = *(unsigned short*)&h;
                asm volatile("st.shared.b16 [%0], %1;" :: "r"(addr), "h"(hs));
            }
        }
    }

    // ---- mainloop ----
    float acc[2][2][4][4];
#pragma unroll
    for (int jj = 0; jj < 2; jj++)
#pragma unroll
        for (int mt = 0; mt < 2; mt++)
#pragma unroll
            for (int j = 0; j < 4; j++)
#pragma unroll
                for (int e = 0; e < 4; e++) acc[jj][mt][j][e] = 0.f;

    uint32_t arel[2];
#pragma unroll
    for (int mt = 0; mt < 2; mt++)
        arel[mt] = (uint32_t)((mt * 16 + (lane & 15)) * APITCHB + (lane >> 4) * 16);

    for (int k = 0; k < KT; k++) {
        if (k < KT - 1) asm volatile("cp.async.wait_group 1;" ::: "memory");
        else            asm volatile("cp.async.wait_group 0;" ::: "memory");
        __syncthreads();                               // stage k + X visible; tap k-1 reads done
        if (k + 2 < KT)
            cp_tile(sb + SM_W + (uint32_t)(((k + 2) % 3) * WIMG),
                    wg + (size_t)(k + 2) * WIMG, tid);

        uint32_t aimg = sb + SM_W + (uint32_t)((k % 3) * WIMG);
        uint32_t ub[4], sw[4];
#pragma unroll
        for (int j = 0; j < 4; j++) {
            int u = nbase + j * 8 + q + k + 1;         // row of x[t_out + k - 7]
            ub[j] = sb + SM_X + (uint32_t)(u << 8);
            sw[j] = xsw(u);
        }
#pragma unroll
        for (int o = 0; o < 8; o++) {
            // B fragments: two conflict-free LDS32 per j (R10 addressing)
            uint32_t bx[4][2];
#pragma unroll
            for (int j = 0; j < 4; j++) {
                uint32_t c0 = (uint32_t)(o * 8 + r4);
                uint32_t ad0 = ub[j] + ((c0 ^ sw[j]) << 2);
                asm volatile("ld.shared.b32 %0, [%1];" : "=r"(bx[j][0]) : "r"(ad0));
                asm volatile("ld.shared.b32 %0, [%1];" : "=r"(bx[j][1]) : "r"(ad0 ^ 16));
            }
            uint32_t A0[4], A1[4], A2[4], A3[4];
            if (o < 6) {
                ldm4(A0, aimg + arel[0] + (uint32_t)(o * 32));
                ldm4(A1, aimg + arel[1] + (uint32_t)(o * 32));
            }
            if (o >= 2) {
                ldm4(A2, aimg + AIMG1 + arel[0] + (uint32_t)((o - 2) * 32));
                ldm4(A3, aimg + AIMG1 + arel[1] + (uint32_t)((o - 2) * 32));
            }
#pragma unroll
            for (int j = 0; j < 4; j++) {
                if (o < 6) {
                    mma16816(acc[0][0][j], A0, bx[j][0], bx[j][1]);
                    mma16816(acc[0][1][j], A1, bx[j][0], bx[j][1]);
                }
                if (o >= 2) {
                    mma16816(acc[1][0][j], A2, bx[j][0], bx[j][1]);
                    mma16816(acc[1][1][j], A3, bx[j][0], bx[j][1]);
                }
            }
        }
    }

    __syncthreads();   // all B/A reads done before smem reuse as ybuf

    // ---- epilogue: pool jj0+jj1 + bias + LeakyReLU -> ybuf -> coalesced STG
    float bp[2][2];
#pragma unroll
    for (int mt = 0; mt < 2; mt++)
#pragma unroll
        for (int h = 0; h < 2; h++) {
            int ch = mt * 16 + h * 8 + q;
            bp[mt][h] = 0.5f * (bias[g * 64 + ch] + bias[g * 64 + 32 + ch]);
        }
    float* ybuf = (float*)smem;
#pragma unroll
    for (int mt = 0; mt < 2; mt++)
#pragma unroll
        for (int j = 0; j < 4; j++) {
            int col = nbase + j * 8 + 2 * r4;
#pragma unroll
            for (int h = 0; h < 2; h++) {
                float p0 = 0.5f * (acc[0][mt][j][2 * h]     + acc[1][mt][j][2 * h])     + bp[mt][h];
                float p1 = 0.5f * (acc[0][mt][j][2 * h + 1] + acc[1][mt][j][2 * h + 1]) + bp[mt][h];
                p0 = (p0 >= 0.f) ? p0 : NEG * p0;
                p1 = (p1 >= 0.f) ? p1 : NEG * p1;
                int ch = mt * 16 + h * 8 + q;
                *(float2*)&ybuf[ch * YPITCH + col] = make_float2(p0, p1);
            }
        }
    __syncthreads();
#pragma unroll
    for (int it = 0; it < 8; it++) {
        int f = it * 256 + tid;
        int row = f >> 6, c4 = (f & 63) << 2;
        float4 v = *(float4*)&ybuf[row * YPITCH + c4];
        *(float4*)(out + ((size_t)b * (NP * Cc) + g * Cc + row) * Tn + t0 + c4) = v;
    }
}

// ---------------- launch ----------------
extern "C" void kernel_launch(void* const* d_in, const int* in_sizes, int n_in,
                              void* d_out, int out_size) {
    const float* x    = (const float*)d_in[0];
    const float* w    = (const float*)d_in[1];
    const float* bias = (const float*)d_in[2];
    // d_in[3] = mask (static block-tridiagonal), d_in[4] = pool_pairs (consecutive)
    float* out = (float*)d_out;

    cudaFuncSetAttribute(skel_hmma_kernel,
                         cudaFuncAttributeMaxDynamicSharedMemorySize, SM_TOTAL);

    repack_w<<<NP * KT, 256>>>(w);
    dim3 grid(Tn / TT, NP, Bn);
    skel_hmma_kernel<<<grid, 256, SM_TOTAL>>>(x, bias, out);
}